// round 15
// baseline (speedup 1.0000x reference)
#include <cuda_runtime.h>

// VectorQuantizer: z [B,64] f32, codebook [1024,64] f32
// out = concat( z_q_st [B*64], vq_loss [1], indices-as-float [B] )

typedef unsigned long long u64;

#define K_CODES 1024
#define D 64
#define THREADS 128
#define ROWS_CTA 256
#define CHUNK 128
#define NCHUNK (K_CODES/CHUNK)
#define TR 8                     // rows per lane (interleaved stride 32)
#define TC 8                     // codes per tile
#define RSW 68                   // z row stride in words (conflict-free: 68 mod 32 = 4)

__device__ double   g_loss;
__device__ unsigned g_done;
__device__ float    g_c2[K_CODES];

static __device__ __forceinline__ void unpack2(u64 v, float& x, float& y) {
    asm("mov.b64 {%0,%1},%2;" : "=f"(x), "=f"(y) : "l"(v));
}
static __device__ __forceinline__ u64 ffma2(u64 a, u64 b, u64 c) {
    u64 d; asm("fma.rn.f32x2 %0,%1,%2,%3;" : "=l"(d) : "l"(a), "l"(b), "l"(c)); return d;
}

// Prep: c2 (pairwise tree, bitwise stable since R1), zero loss + done counter.
__global__ void vq_prep(const float* __restrict__ cb) {
    __shared__ float s[D];
    int k = blockIdx.x, d = threadIdx.x;
    float v = cb[k * D + d];
    s[d] = v * v;
    __syncthreads();
#pragma unroll
    for (int off = D / 2; off >= 1; off >>= 1) {
        if (d < off) s[d] = s[d] + s[d + off];
        __syncthreads();
    }
    if (d == 0) {
        g_c2[k] = s[0];
        if (k == 0) { g_loss = 0.0; g_done = 0u; }
    }
}

__global__ void __launch_bounds__(THREADS, 2)
vq_main(const float* __restrict__ z, const float* __restrict__ cb,
        float* __restrict__ out, int B, int out_size) {
    extern __shared__ float sm[];
    float* s_zw = sm;                          // [256 rows][RSW] z tile (words)
    float* s_c  = s_zw + ROWS_CTA * RSW;       // [CHUNK][64] codebook chunk
    float* s_c2 = s_c + CHUNK * D;             // [1024]
    float* s_z2 = s_c2 + K_CODES;              // [256]
    // overlays inside s_c after mainloop:
    float*  candv = s_c;                       // [4][256]
    int*    candi = (int*)(s_c + 4 * ROWS_CTA);// [4][256]
    double* sd    = (double*)(s_c + 8 * ROWS_CTA); // [128]

    const int t    = threadIdx.x;
    const int lane = t & 31;
    const int w    = t >> 5;
    const long base = (long)blockIdx.x * ROWS_CTA;

    // ---- stage z tile (rows t and t+128) + z2 (R1 tree, bitwise) ----
#pragma unroll
    for (int rr = 0; rr < 2; rr++) {
        const int R = t + rr * THREADS;
        const float4* a4 = (const float4*)(z + (base + R) * D);
        float s[32];
#pragma unroll
        for (int i4 = 0; i4 < 16; i4++) {
            float4 a = a4[i4];
            *(float4*)(s_zw + (size_t)R * RSW + 4 * i4) = a;
            s[2 * i4 + 0] = a.x * a.x + a.y * a.y;
            s[2 * i4 + 1] = a.z * a.z + a.w * a.w;
        }
#pragma unroll
        for (int off = 16; off >= 1; off >>= 1)
#pragma unroll
            for (int i = 0; i < off; i++) s[i] = s[i] + s[i + off];
        s_z2[R] = s[0];
    }
#pragma unroll
    for (int i = t; i < K_CODES; i += THREADS) s_c2[i] = g_c2[i];
    __syncthreads();

    // z2 for this lane's 8 rows (rows lane + 32j)
    float z2r[TR];
#pragma unroll
    for (int j = 0; j < TR; j++) z2r[j] = s_z2[lane + 32 * j];

    float mv[TR];
    int   mi[TR];
#pragma unroll
    for (int j = 0; j < TR; j++) { mv[j] = 3.402823466e38f; mi[j] = 0; }

    for (int ch = 0; ch < NCHUNK; ++ch) {
        __syncthreads();
        // stage codebook chunk (plain coalesced float4 copy, stride 64 words)
        {
            const float4* src = (const float4*)(cb + (size_t)ch * CHUNK * D);
            float4* dst = (float4*)s_c;
#pragma unroll
            for (int it = 0; it < CHUNK * (D / 4) / THREADS; it++)
                dst[it * THREADS + t] = src[it * THREADS + t];
        }
        __syncthreads();

#pragma unroll
        for (int tile = 0; tile < CHUNK / (4 * TC); tile++) {
            const int kb = w * (CHUNK / 4) + tile * TC;   // code offset within chunk
            u64 acc[TR][TC];
#pragma unroll
            for (int j = 0; j < TR; j++)
#pragma unroll
                for (int j2 = 0; j2 < TC; j2++) acc[j][j2] = 0ull;

#pragma unroll
            for (int i = 0; i < 16; i++) {                // 16B = dims 4i..4i+3
                ulonglong2 cc[TC];
#pragma unroll
                for (int j2 = 0; j2 < TC; j2++)
                    cc[j2] = *(const ulonglong2*)(s_c + (size_t)(kb + j2) * D + 4 * i);
#pragma unroll
                for (int j = 0; j < TR; j++) {
                    ulonglong2 zz = *(const ulonglong2*)(s_zw + (size_t)(lane + 32 * j) * RSW + 4 * i);
#pragma unroll
                    for (int j2 = 0; j2 < TC; j2++) {
                        acc[j][j2] = ffma2(zz.x, cc[j2].x, acc[j][j2]);  // even dims lane0
                        acc[j][j2] = ffma2(zz.y, cc[j2].y, acc[j][j2]);  // odd dims lane1
                    }
                }
            }

#pragma unroll
            for (int j2 = 0; j2 < TC; j2++) {
                const int k = ch * CHUNK + kb + j2;
                const float c2s = s_c2[k];                // global index (R12 lesson)
#pragma unroll
                for (int j = 0; j < TR; j++) {
                    float e, o;
                    unpack2(acc[j][j2], e, o);
                    float dv = fmaf(-2.0f, e + o, z2r[j]) + c2s;  // 2*cross exact
                    if (dv < mv[j]) { mv[j] = dv; mi[j] = k; }    // strict < in-warp
                }
            }
        }
    }

    // ---- cross-warp argmin combine (4 warps per row), idx tie-break ----
    __syncthreads();   // all reads of s_c done -> safe to overlay
#pragma unroll
    for (int j = 0; j < TR; j++) {
        candv[w * ROWS_CTA + lane + 32 * j] = mv[j];
        candi[w * ROWS_CTA + lane + 32 * j] = mi[j];
    }
    __syncthreads();

    double lacc = 0.0;
#pragma unroll
    for (int rr = 0; rr < 2; rr++) {
        const int R = t + rr * THREADS;
        float bv = candv[R];
        int   bi = candi[R];
#pragma unroll
        for (int ww = 1; ww < 4; ww++) {
            float v = candv[ww * ROWS_CTA + R];
            int   i = candi[ww * ROWS_CTA + R];
            if (v < bv || (v == bv && i < bi)) { bv = v; bi = i; }  // first-index wins
        }
        const long row = base + R;
        const float4* qv = (const float4*)(cb + (size_t)bi * D);
        float4* o = (float4*)(out + row * D);
#pragma unroll
        for (int i4 = 0; i4 < 16; i4++) {
            float4 a = qv[i4];
            float4 zv = *(const float4*)(s_zw + (size_t)R * RSW + 4 * i4);
            float d;
            d = a.x - zv.x; lacc += (double)(d * d);
            d = a.y - zv.y; lacc += (double)(d * d);
            d = a.z - zv.z; lacc += (double)(d * d);
            d = a.w - zv.w; lacc += (double)(d * d);
            o[i4] = a;
        }
        if ((long)out_size >= (long)B * D + 1 + B)
            out[(long)B * D + 1 + row] = (float)bi;
    }

    // ---- block-reduce loss, last CTA finalizes ----
    __syncthreads();
    sd[t] = lacc;
    __syncthreads();
#pragma unroll
    for (int off = THREADS / 2; off >= 1; off >>= 1) {
        if (t < off) sd[t] += sd[t + off];
        __syncthreads();
    }
    if (t == 0) {
        atomicAdd(&g_loss, sd[0]);
        __threadfence();
        unsigned v = atomicAdd(&g_done, 1u);
        if (v == gridDim.x - 1) {
            g_done = 0u;
            if ((long)out_size >= (long)B * D + 1) {
                float m = (float)(g_loss / (double)((long)B * D));
                out[(size_t)B * D] = m + 0.25f * m;
            }
        }
    }
}

extern "C" void kernel_launch(void* const* d_in, const int* in_sizes, int n_in,
                              void* d_out, int out_size) {
    const float* z  = (const float*)d_in[0];
    const float* cb = (const float*)d_in[1];
    float* out = (float*)d_out;
    const int B = in_sizes[0] / D;

    const size_t smem = ((size_t)ROWS_CTA * RSW + (size_t)CHUNK * D
                       + K_CODES + ROWS_CTA) * sizeof(float);
    cudaFuncSetAttribute(vq_main, cudaFuncAttributeMaxDynamicSharedMemorySize, (int)smem);

    vq_prep<<<K_CODES, D>>>(cb);
    vq_main<<<B / ROWS_CTA, THREADS, smem>>>(z, cb, out, B, out_size);
}

// round 16
// speedup vs baseline: 5.5341x; 5.5341x over previous
#include <cuda_runtime.h>

// VectorQuantizer: z [B,64] f32, codebook [1024,64] f32
// out = concat( z_q_st [B*64], vq_loss [1], indices-as-float [B] )
//
// Phase plan: c2-prep, z2-prep, bf16-split codebook prep, MMA main (approx top-2
// with certified-gap test), exact rescore of flagged rows, loss finish.

typedef unsigned int uint;
typedef unsigned long long u64;

#define K_CODES 1024
#define D 64
#define BMAX 262144
#define CSTR 36                 // u32 stride per code per bf16 buffer (bank-padded)
#define CHUNKM 256              // codes per smem chunk in MMA kernel
#define THR 1.6e-4f             // certified gap threshold (>=8x error bound)
#define FLTMAX 3.402823466e38f

__device__ double   g_loss;
__device__ unsigned g_nflag;
__device__ float    g_c2[K_CODES];
__device__ float    g_z2[BMAX];
__device__ int      g_flist[BMAX];
__device__ uint     g_cbh[K_CODES * CSTR];
__device__ uint     g_cbl[K_CODES * CSTR];

static __device__ __forceinline__ uint bf2pack(float lo, float hi) {
    uint r; asm("cvt.rn.bf16x2.f32 %0,%1,%2;" : "=r"(r) : "f"(hi), "f"(lo)); return r;
}
static __device__ __forceinline__ void mma_bf16(float& d0, float& d1, float& d2, float& d3,
                                                uint a0, uint a1, uint a2, uint a3,
                                                uint b0, uint b1) {
    asm("mma.sync.aligned.m16n8k16.row.col.f32.bf16.bf16.f32 "
        "{%0,%1,%2,%3},{%4,%5,%6,%7},{%8,%9},{%0,%1,%2,%3};"
        : "+f"(d0), "+f"(d1), "+f"(d2), "+f"(d3)
        : "r"(a0), "r"(a1), "r"(a2), "r"(a3), "r"(b0), "r"(b1));
}
// split fp32 pair -> bf16x2 hi + bf16x2 lo (residual exact in fp32)
static __device__ __forceinline__ void split2(float2 v, uint& h, uint& l) {
    h = bf2pack(v.x, v.y);
    float flo = __uint_as_float(h << 16);
    float fhi = __uint_as_float(h & 0xffff0000u);
    l = bf2pack(v.x - flo, v.y - fhi);
}

// ---- prep: c2 per code (R1 pairwise tree), zero loss/flag counters ----
__global__ void vq_prep(const float* __restrict__ cb) {
    __shared__ float s[D];
    int k = blockIdx.x, d = threadIdx.x;
    float v = cb[k * D + d];
    s[d] = v * v;
    __syncthreads();
#pragma unroll
    for (int off = D / 2; off >= 1; off >>= 1) {
        if (d < off) s[d] = s[d] + s[d + off];
        __syncthreads();
    }
    if (d == 0) {
        g_c2[k] = s[0];
        if (k == 0) { g_loss = 0.0; g_nflag = 0u; }
    }
}

// ---- prep: z2 per row (exact R1 pairwise tree) ----
__global__ void vq_z2k(const float* __restrict__ z, int B) {
    long r = (long)blockIdx.x * 128 + threadIdx.x;
    if (r >= B) return;
    const float4* a4 = (const float4*)(z + r * D);
    float s[32];
#pragma unroll
    for (int i4 = 0; i4 < 16; i4++) {
        float4 a = a4[i4];
        s[2 * i4 + 0] = a.x * a.x + a.y * a.y;
        s[2 * i4 + 1] = a.z * a.z + a.w * a.w;
    }
#pragma unroll
    for (int off = 16; off >= 1; off >>= 1)
#pragma unroll
        for (int i = 0; i < off; i++) s[i] = s[i] + s[i + off];
    g_z2[r] = s[0];
}

// ---- prep: split codebook to bf16 hi/lo in permuted B-fragment layout ----
// pair p of code k -> slot 8s + (w<4 ? 2w : 2(w-4)+1), s=p>>3, w=p&7, so that
// (b0,b1) for (kstep s, q=lane%4) are adjacent u32s at k*CSTR + 8s + 2q.
__global__ void vq_cvt(const float* __restrict__ cb) {
    int k = blockIdx.x, p = threadIdx.x;   // 32 threads = 32 dim-pairs
    float2 v = *(const float2*)(cb + k * D + 2 * p);
    uint h, l;
    split2(v, h, l);
    int s = p >> 3, w = p & 7;
    int slot = 8 * s + ((w < 4) ? 2 * w : 2 * (w - 4) + 1);
    g_cbh[k * CSTR + slot] = h;
    g_cbl[k * CSTR + slot] = l;
}

// per-(row) running top-2 update / merge helpers
static __device__ __forceinline__ void upd2(float& m1, int& i1, float& m2, float dv, int k) {
    if (dv < m1) { m2 = m1; m1 = dv; i1 = k; }
    else if (dv < m2) m2 = dv;
}

// ---- main: bf16-split MMA distances, certified top-2 gap test ----
__global__ void __launch_bounds__(128, 2)
vq_mma(const float* __restrict__ z, const float* __restrict__ cb,
       float* __restrict__ out, int B, int out_size) {
    extern __shared__ char smraw[];
    uint*  s_h  = (uint*)smraw;                       // [CHUNKM*CSTR]
    uint*  s_l  = s_h + CHUNKM * CSTR;
    float* s_c2 = (float*)(s_l + CHUNKM * CSTR);      // [1024]
    double* sd  = (double*)smraw;                     // overlay for loss reduce

    const int t = threadIdx.x, lane = t & 31, w = t >> 5;
    const int g = lane >> 2, q = lane & 3;
    const long base = (long)blockIdx.x * 64;
    const long row0 = base + w * 16 + g;
    const long row1 = row0 + 8;

    // Build A fragments once: reg order {a0,a1,a2,a3} = (rowg,klo),(rowg+8,klo),(rowg,khi),(rowg+8,khi)
    uint Ah[4][4], Al[4][4];
#pragma unroll
    for (int s = 0; s < 4; s++) {
        float2 v0 = *(const float2*)(z + row0 * D + 16 * s + 2 * q);
        float2 v1 = *(const float2*)(z + row0 * D + 16 * s + 8 + 2 * q);
        float2 v2 = *(const float2*)(z + row1 * D + 16 * s + 2 * q);
        float2 v3 = *(const float2*)(z + row1 * D + 16 * s + 8 + 2 * q);
        split2(v0, Ah[s][0], Al[s][0]);
        split2(v2, Ah[s][1], Al[s][1]);
        split2(v1, Ah[s][2], Al[s][2]);
        split2(v3, Ah[s][3], Al[s][3]);
    }
    const float z2a = g_z2[row0], z2b = g_z2[row1];

#pragma unroll
    for (int i = t; i < K_CODES; i += 128) s_c2[i] = g_c2[i];

    float m1a = FLTMAX, m2a = FLTMAX, m1b = FLTMAX, m2b = FLTMAX;
    int   i1a = 0, i1b = 0;

    for (int ch = 0; ch < K_CODES / CHUNKM; ch++) {
        __syncthreads();
        {
            const float4* sh = (const float4*)(g_cbh + (size_t)ch * CHUNKM * CSTR);
            const float4* sl = (const float4*)(g_cbl + (size_t)ch * CHUNKM * CSTR);
            float4* dh = (float4*)s_h; float4* dl = (float4*)s_l;
            for (int i = t; i < CHUNKM * CSTR / 4; i += 128) { dh[i] = sh[i]; dl[i] = sl[i]; }
        }
        __syncthreads();

        for (int tg = 0; tg < CHUNKM / 32; tg++) {       // 4 tiles x 8 codes
            float acc[4][4];
#pragma unroll
            for (int tt = 0; tt < 4; tt++)
#pragma unroll
                for (int e = 0; e < 4; e++) acc[tt][e] = 0.f;

#pragma unroll
            for (int s = 0; s < 4; s++) {
#pragma unroll
                for (int tt = 0; tt < 4; tt++) {
                    int code = tg * 32 + tt * 8 + g;      // B col = lane>>2
                    const uint* pb = s_h + (size_t)code * CSTR + 8 * s + 2 * q;
                    uint2 bh = *(const uint2*)pb;
                    const uint* pl = s_l + (size_t)code * CSTR + 8 * s + 2 * q;
                    uint2 bl = *(const uint2*)pl;
                    mma_bf16(acc[tt][0], acc[tt][1], acc[tt][2], acc[tt][3],
                             Ah[s][0], Ah[s][1], Ah[s][2], Ah[s][3], bh.x, bh.y);
                    mma_bf16(acc[tt][0], acc[tt][1], acc[tt][2], acc[tt][3],
                             Ah[s][0], Ah[s][1], Ah[s][2], Ah[s][3], bl.x, bl.y);
                    mma_bf16(acc[tt][0], acc[tt][1], acc[tt][2], acc[tt][3],
                             Al[s][0], Al[s][1], Al[s][2], Al[s][3], bh.x, bh.y);
                    mma_bf16(acc[tt][0], acc[tt][1], acc[tt][2], acc[tt][3],
                             Al[s][0], Al[s][1], Al[s][2], Al[s][3], bl.x, bl.y);
                }
            }
#pragma unroll
            for (int tt = 0; tt < 4; tt++) {
                int kg = ch * CHUNKM + tg * 32 + tt * 8 + 2 * q;  // D col = 2q,2q+1
                float c20 = s_c2[kg], c21 = s_c2[kg + 1];
                float dv;
                dv = fmaf(-2.f, acc[tt][0], z2a) + c20; upd2(m1a, i1a, m2a, dv, kg);
                dv = fmaf(-2.f, acc[tt][1], z2a) + c21; upd2(m1a, i1a, m2a, dv, kg + 1);
                dv = fmaf(-2.f, acc[tt][2], z2b) + c20; upd2(m1b, i1b, m2b, dv, kg);
                dv = fmaf(-2.f, acc[tt][3], z2b) + c21; upd2(m1b, i1b, m2b, dv, kg + 1);
            }
        }
    }

    // quad combine (lanes 4g..4g+3): top-2 merge with first-index tie-break
#pragma unroll
    for (int dx = 1; dx <= 2; dx <<= 1) {
        float om1 = __shfl_xor_sync(0xffffffffu, m1a, dx);
        int   oi1 = __shfl_xor_sync(0xffffffffu, i1a, dx);
        float om2 = __shfl_xor_sync(0xffffffffu, m2a, dx);
        if (om1 < m1a || (om1 == m1a && oi1 < i1a)) { m2a = fminf(m1a, om2); m1a = om1; i1a = oi1; }
        else m2a = fminf(m2a, om1);
        om1 = __shfl_xor_sync(0xffffffffu, m1b, dx);
        oi1 = __shfl_xor_sync(0xffffffffu, i1b, dx);
        om2 = __shfl_xor_sync(0xffffffffu, m2b, dx);
        if (om1 < m1b || (om1 == m1b && oi1 < i1b)) { m2b = fminf(m1b, om2); m1b = om1; i1b = oi1; }
        else m2b = fminf(m2b, om1);
    }

    // epilogue: certified rows written here; uncertain rows flagged
    double lacc = 0.0;
    const long iofs = (long)B * D + 1;
    const bool room = ((long)out_size >= (long)B * D + 1 + B);
#pragma unroll
    for (int rr = 0; rr < 2; rr++) {
        long  row = rr ? row1 : row0;
        float m1 = rr ? m1b : m1a, m2 = rr ? m2b : m2a;
        int   i1 = rr ? i1b : i1a;
        if (m2 - m1 <= THR) {
            if (q == 0) { unsigned p = atomicAdd(&g_nflag, 1u); g_flist[p] = (int)row; }
        } else {
            const float4* cq = (const float4*)(cb + (size_t)i1 * D + q * 16);
            const float4* zq = (const float4*)(z + row * D + q * 16);
            float4* o = (float4*)(out + row * D + q * 16);
#pragma unroll
            for (int i = 0; i < 4; i++) {
                float4 a = cq[i], zz = zq[i];
                float d;
                d = a.x - zz.x; lacc += (double)(d * d);
                d = a.y - zz.y; lacc += (double)(d * d);
                d = a.z - zz.z; lacc += (double)(d * d);
                d = a.w - zz.w; lacc += (double)(d * d);
                o[i] = a;
            }
            if (q == 0 && room) out[iofs + row] = (float)i1;
        }
    }

    __syncthreads();           // done with s_h -> overlay
    sd[t] = lacc;
    __syncthreads();
#pragma unroll
    for (int off = 64; off >= 1; off >>= 1) {
        if (t < off) sd[t] += sd[t + off];
        __syncthreads();
    }
    if (t == 0) atomicAdd(&g_loss, sd[0]);
}

// ---- rescore flagged rows with the exact (R10-bitwise) recipe ----
__global__ void __launch_bounds__(256, 1)
vq_rescore(const float* __restrict__ z, const float* __restrict__ cb,
           float* __restrict__ out, int B, int out_size) {
    extern __shared__ float sm[];
    float*  s_cb = sm;                      // [256][68]
    float*  s_z  = sm + 256 * 68;           // [8][64]
    double* sdr  = (double*)(s_z + 8 * 64); // [256]

    const int t = threadIdx.x, lane = t & 31, w = t >> 5;
    const unsigned nf = g_nflag;
    const unsigned per = gridDim.x * 8;
    const unsigned T = (nf + per - 1) / per;
    double lacc = 0.0;

    for (unsigned it = 0; it < T; it++) {
        unsigned fi = (blockIdx.x + it * gridDim.x) * 8 + w;
        const bool act = fi < nf;
        long row = act ? (long)g_flist[fi] : 0;
        __syncthreads();
        if (act) {
            s_z[w * 64 + lane]      = z[row * D + lane];
            s_z[w * 64 + 32 + lane] = z[row * D + 32 + lane];
        }
        __syncwarp();
        float z2 = act ? g_z2[row] : 0.f;
        float m1 = FLTMAX; int i1 = 0;

        for (int ch = 0; ch < 4; ch++) {
            __syncthreads();
            for (int i = t; i < 256 * 16; i += 256) {
                int c = i >> 4, f = i & 15;
                *(float4*)(s_cb + (size_t)c * 68 + 4 * f) =
                    *(const float4*)(cb + ((size_t)ch * 256 + c) * D + 4 * f);
            }
            __syncthreads();
            if (act) {
                for (int j = 0; j < 8; j++) {
                    int kl = lane + 32 * j;
                    int k = ch * 256 + kl;
                    const float2* cp = (const float2*)(s_cb + (size_t)kl * 68);
                    float e = 0.f, o = 0.f;
#pragma unroll
                    for (int i2 = 0; i2 < 32; i2++) {
                        float2 c = cp[i2];
                        float2 zz = *(const float2*)(s_z + w * 64 + 2 * i2);
                        e = fmaf(zz.x, c.x, e);
                        o = fmaf(zz.y, c.y, o);
                    }
                    float dv = fmaf(-2.f, e + o, z2) + g_c2[k];
                    if (dv < m1) { m1 = dv; i1 = k; }   // ascending k per lane
                }
            }
        }
        // warp argmin with first-index tie-break
#pragma unroll
        for (int dx = 16; dx >= 1; dx >>= 1) {
            float ov = __shfl_xor_sync(0xffffffffu, m1, dx);
            int   oi = __shfl_xor_sync(0xffffffffu, i1, dx);
            if (ov < m1 || (ov == m1 && oi < i1)) { m1 = ov; i1 = oi; }
        }
        if (act) {
            float c0 = cb[(size_t)i1 * D + lane], c1 = cb[(size_t)i1 * D + 32 + lane];
            out[row * D + lane] = c0;
            out[row * D + 32 + lane] = c1;
            float d0 = c0 - s_z[w * 64 + lane], d1 = c1 - s_z[w * 64 + 32 + lane];
            lacc += (double)(d0 * d0) + (double)(d1 * d1);
            if (lane == 0 && (long)out_size >= (long)B * D + 1 + B)
                out[(long)B * D + 1 + row] = (float)i1;
        }
    }

    __syncthreads();
    sdr[t] = lacc;
    __syncthreads();
#pragma unroll
    for (int off = 128; off >= 1; off >>= 1) {
        if (t < off) sdr[t] += sdr[t + off];
        __syncthreads();
    }
    if (t == 0 && sdr[0] != 0.0) atomicAdd(&g_loss, sdr[0]);
}

__global__ void vq_finish(float* __restrict__ out, int B, int out_size) {
    if ((long)out_size >= (long)B * D + 1) {
        float m = (float)(g_loss / (double)((long)B * D));
        out[(size_t)B * D] = m + 0.25f * m;
    }
}

extern "C" void kernel_launch(void* const* d_in, const int* in_sizes, int n_in,
                              void* d_out, int out_size) {
    const float* z  = (const float*)d_in[0];
    const float* cb = (const float*)d_in[1];
    float* out = (float*)d_out;
    const int B = in_sizes[0] / D;

    const size_t smemM = (size_t)2 * CHUNKM * CSTR * 4 + K_CODES * 4;
    const size_t smemR = (size_t)256 * 68 * 4 + 8 * 64 * 4 + 256 * 8;
    cudaFuncSetAttribute(vq_mma, cudaFuncAttributeMaxDynamicSharedMemorySize, (int)smemM);
    cudaFuncSetAttribute(vq_rescore, cudaFuncAttributeMaxDynamicSharedMemorySize, (int)smemR);

    vq_prep<<<K_CODES, D>>>(cb);
    vq_z2k<<<(B + 127) / 128, 128>>>(z, B);
    vq_cvt<<<K_CODES, 32>>>(cb);
    vq_mma<<<B / 64, 128, smemM>>>(z, cb, out, B, out_size);
    vq_rescore<<<1024, 256, smemR>>>(z, cb, out, B, out_size);
    vq_finish<<<1, 1>>>(out, B, out_size);
}

// round 17
// speedup vs baseline: 5.5427x; 1.0016x over previous
#include <cuda_runtime.h>

// VectorQuantizer: z [B,64] f32, codebook [1024,64] f32
// out = concat( z_q_st [B*64], vq_loss [1], indices-as-float [B] )
//
// Phase plan: c2-prep, z2-prep, bf16-split codebook prep, MMA main (approx top-2
// with certified-gap test), exact rescore of flagged rows, loss finish.

typedef unsigned int uint;
typedef unsigned long long u64;

#define K_CODES 1024
#define D 64
#define BMAX 262144
#define CSTR 36                 // u32 stride per code per bf16 buffer (bank-padded)
#define CHUNKM 256              // codes per smem chunk in MMA kernel
#define THR 1.6e-4f             // certified gap threshold (>=8x error bound)
#define FLTMAX 3.402823466e38f

__device__ double   g_loss;
__device__ unsigned g_nflag;
__device__ float    g_c2[K_CODES];
__device__ float    g_z2[BMAX];
__device__ int      g_flist[BMAX];
__device__ uint     g_cbh[K_CODES * CSTR];
__device__ uint     g_cbl[K_CODES * CSTR];

static __device__ __forceinline__ uint bf2pack(float lo, float hi) {
    uint r; asm("cvt.rn.bf16x2.f32 %0,%1,%2;" : "=r"(r) : "f"(hi), "f"(lo)); return r;
}
static __device__ __forceinline__ void mma_bf16(float& d0, float& d1, float& d2, float& d3,
                                                uint a0, uint a1, uint a2, uint a3,
                                                uint b0, uint b1) {
    asm("mma.sync.aligned.m16n8k16.row.col.f32.bf16.bf16.f32 "
        "{%0,%1,%2,%3},{%4,%5,%6,%7},{%8,%9},{%0,%1,%2,%3};"
        : "+f"(d0), "+f"(d1), "+f"(d2), "+f"(d3)
        : "r"(a0), "r"(a1), "r"(a2), "r"(a3), "r"(b0), "r"(b1));
}
// split fp32 pair -> bf16x2 hi + bf16x2 lo (residual exact in fp32)
static __device__ __forceinline__ void split2(float2 v, uint& h, uint& l) {
    h = bf2pack(v.x, v.y);
    float flo = __uint_as_float(h << 16);
    float fhi = __uint_as_float(h & 0xffff0000u);
    l = bf2pack(v.x - flo, v.y - fhi);
}

// ---- prep: c2 per code (R1 pairwise tree), zero loss/flag counters ----
__global__ void vq_prep(const float* __restrict__ cb) {
    __shared__ float s[D];
    int k = blockIdx.x, d = threadIdx.x;
    float v = cb[k * D + d];
    s[d] = v * v;
    __syncthreads();
#pragma unroll
    for (int off = D / 2; off >= 1; off >>= 1) {
        if (d < off) s[d] = s[d] + s[d + off];
        __syncthreads();
    }
    if (d == 0) {
        g_c2[k] = s[0];
        if (k == 0) { g_loss = 0.0; g_nflag = 0u; }
    }
}

// ---- prep: z2 per row (exact R1 pairwise tree) ----
__global__ void vq_z2k(const float* __restrict__ z, int B) {
    long r = (long)blockIdx.x * 128 + threadIdx.x;
    if (r >= B) return;
    const float4* a4 = (const float4*)(z + r * D);
    float s[32];
#pragma unroll
    for (int i4 = 0; i4 < 16; i4++) {
        float4 a = a4[i4];
        s[2 * i4 + 0] = a.x * a.x + a.y * a.y;
        s[2 * i4 + 1] = a.z * a.z + a.w * a.w;
    }
#pragma unroll
    for (int off = 16; off >= 1; off >>= 1)
#pragma unroll
        for (int i = 0; i < off; i++) s[i] = s[i] + s[i + off];
    g_z2[r] = s[0];
}

// ---- prep: split codebook to bf16 hi/lo in permuted B-fragment layout ----
// pair p of code k -> slot 8s + (w<4 ? 2w : 2(w-4)+1), s=p>>3, w=p&7, so that
// (b0,b1) for (kstep s, q=lane%4) are adjacent u32s at k*CSTR + 8s + 2q.
__global__ void vq_cvt(const float* __restrict__ cb) {
    int k = blockIdx.x, p = threadIdx.x;   // 32 threads = 32 dim-pairs
    float2 v = *(const float2*)(cb + k * D + 2 * p);
    uint h, l;
    split2(v, h, l);
    int s = p >> 3, w = p & 7;
    int slot = 8 * s + ((w < 4) ? 2 * w : 2 * (w - 4) + 1);
    g_cbh[k * CSTR + slot] = h;
    g_cbl[k * CSTR + slot] = l;
}

// per-(row) running top-2 update / merge helpers
static __device__ __forceinline__ void upd2(float& m1, int& i1, float& m2, float dv, int k) {
    if (dv < m1) { m2 = m1; m1 = dv; i1 = k; }
    else if (dv < m2) m2 = dv;
}

// ---- main: bf16-split MMA distances, certified top-2 gap test ----
__global__ void __launch_bounds__(128, 2)
vq_mma(const float* __restrict__ z, const float* __restrict__ cb,
       float* __restrict__ out, int B, int out_size) {
    extern __shared__ char smraw[];
    uint*  s_h  = (uint*)smraw;                       // [CHUNKM*CSTR]
    uint*  s_l  = s_h + CHUNKM * CSTR;
    float* s_c2 = (float*)(s_l + CHUNKM * CSTR);      // [1024]
    double* sd  = (double*)smraw;                     // overlay for loss reduce

    const int t = threadIdx.x, lane = t & 31, w = t >> 5;
    const int g = lane >> 2, q = lane & 3;
    const long base = (long)blockIdx.x * 64;
    const long row0 = base + w * 16 + g;
    const long row1 = row0 + 8;

    // Build A fragments once: reg order {a0,a1,a2,a3} = (rowg,klo),(rowg+8,klo),(rowg,khi),(rowg+8,khi)
    uint Ah[4][4], Al[4][4];
#pragma unroll
    for (int s = 0; s < 4; s++) {
        float2 v0 = *(const float2*)(z + row0 * D + 16 * s + 2 * q);
        float2 v1 = *(const float2*)(z + row0 * D + 16 * s + 8 + 2 * q);
        float2 v2 = *(const float2*)(z + row1 * D + 16 * s + 2 * q);
        float2 v3 = *(const float2*)(z + row1 * D + 16 * s + 8 + 2 * q);
        split2(v0, Ah[s][0], Al[s][0]);
        split2(v2, Ah[s][1], Al[s][1]);
        split2(v1, Ah[s][2], Al[s][2]);
        split2(v3, Ah[s][3], Al[s][3]);
    }
    const float z2a = g_z2[row0], z2b = g_z2[row1];

#pragma unroll
    for (int i = t; i < K_CODES; i += 128) s_c2[i] = g_c2[i];

    float m1a = FLTMAX, m2a = FLTMAX, m1b = FLTMAX, m2b = FLTMAX;
    int   i1a = 0, i1b = 0;

    for (int ch = 0; ch < K_CODES / CHUNKM; ch++) {
        __syncthreads();
        {
            const float4* sh = (const float4*)(g_cbh + (size_t)ch * CHUNKM * CSTR);
            const float4* sl = (const float4*)(g_cbl + (size_t)ch * CHUNKM * CSTR);
            float4* dh = (float4*)s_h; float4* dl = (float4*)s_l;
            for (int i = t; i < CHUNKM * CSTR / 4; i += 128) { dh[i] = sh[i]; dl[i] = sl[i]; }
        }
        __syncthreads();

        for (int tg = 0; tg < CHUNKM / 32; tg++) {       // 4 tiles x 8 codes
            float acc[4][4];
#pragma unroll
            for (int tt = 0; tt < 4; tt++)
#pragma unroll
                for (int e = 0; e < 4; e++) acc[tt][e] = 0.f;

#pragma unroll
            for (int s = 0; s < 4; s++) {
#pragma unroll
                for (int tt = 0; tt < 4; tt++) {
                    int code = tg * 32 + tt * 8 + g;      // B col = lane>>2
                    const uint* pb = s_h + (size_t)code * CSTR + 8 * s + 2 * q;
                    uint2 bh = *(const uint2*)pb;
                    const uint* pl = s_l + (size_t)code * CSTR + 8 * s + 2 * q;
                    uint2 bl = *(const uint2*)pl;
                    mma_bf16(acc[tt][0], acc[tt][1], acc[tt][2], acc[tt][3],
                             Ah[s][0], Ah[s][1], Ah[s][2], Ah[s][3], bh.x, bh.y);
                    mma_bf16(acc[tt][0], acc[tt][1], acc[tt][2], acc[tt][3],
                             Ah[s][0], Ah[s][1], Ah[s][2], Ah[s][3], bl.x, bl.y);
                    mma_bf16(acc[tt][0], acc[tt][1], acc[tt][2], acc[tt][3],
                             Al[s][0], Al[s][1], Al[s][2], Al[s][3], bh.x, bh.y);
                    mma_bf16(acc[tt][0], acc[tt][1], acc[tt][2], acc[tt][3],
                             Al[s][0], Al[s][1], Al[s][2], Al[s][3], bl.x, bl.y);
                }
            }
#pragma unroll
            for (int tt = 0; tt < 4; tt++) {
                int kg = ch * CHUNKM + tg * 32 + tt * 8 + 2 * q;  // D col = 2q,2q+1
                float c20 = s_c2[kg], c21 = s_c2[kg + 1];
                float dv;
                dv = fmaf(-2.f, acc[tt][0], z2a) + c20; upd2(m1a, i1a, m2a, dv, kg);
                dv = fmaf(-2.f, acc[tt][1], z2a) + c21; upd2(m1a, i1a, m2a, dv, kg + 1);
                dv = fmaf(-2.f, acc[tt][2], z2b) + c20; upd2(m1b, i1b, m2b, dv, kg);
                dv = fmaf(-2.f, acc[tt][3], z2b) + c21; upd2(m1b, i1b, m2b, dv, kg + 1);
            }
        }
    }

    // quad combine (lanes 4g..4g+3): top-2 merge with first-index tie-break
#pragma unroll
    for (int dx = 1; dx <= 2; dx <<= 1) {
        float om1 = __shfl_xor_sync(0xffffffffu, m1a, dx);
        int   oi1 = __shfl_xor_sync(0xffffffffu, i1a, dx);
        float om2 = __shfl_xor_sync(0xffffffffu, m2a, dx);
        if (om1 < m1a || (om1 == m1a && oi1 < i1a)) { m2a = fminf(m1a, om2); m1a = om1; i1a = oi1; }
        else m2a = fminf(m2a, om1);
        om1 = __shfl_xor_sync(0xffffffffu, m1b, dx);
        oi1 = __shfl_xor_sync(0xffffffffu, i1b, dx);
        om2 = __shfl_xor_sync(0xffffffffu, m2b, dx);
        if (om1 < m1b || (om1 == m1b && oi1 < i1b)) { m2b = fminf(m1b, om2); m1b = om1; i1b = oi1; }
        else m2b = fminf(m2b, om1);
    }

    // epilogue: certified rows written here; uncertain rows flagged
    double lacc = 0.0;
    const long iofs = (long)B * D + 1;
    const bool room = ((long)out_size >= (long)B * D + 1 + B);
#pragma unroll
    for (int rr = 0; rr < 2; rr++) {
        long  row = rr ? row1 : row0;
        float m1 = rr ? m1b : m1a, m2 = rr ? m2b : m2a;
        int   i1 = rr ? i1b : i1a;
        if (m2 - m1 <= THR) {
            if (q == 0) { unsigned p = atomicAdd(&g_nflag, 1u); g_flist[p] = (int)row; }
        } else {
            const float4* cq = (const float4*)(cb + (size_t)i1 * D + q * 16);
            const float4* zq = (const float4*)(z + row * D + q * 16);
            float4* o = (float4*)(out + row * D + q * 16);
#pragma unroll
            for (int i = 0; i < 4; i++) {
                float4 a = cq[i], zz = zq[i];
                float d;
                d = a.x - zz.x; lacc += (double)(d * d);
                d = a.y - zz.y; lacc += (double)(d * d);
                d = a.z - zz.z; lacc += (double)(d * d);
                d = a.w - zz.w; lacc += (double)(d * d);
                o[i] = a;
            }
            if (q == 0 && room) out[iofs + row] = (float)i1;
        }
    }

    __syncthreads();           // done with s_h -> overlay
    sd[t] = lacc;
    __syncthreads();
#pragma unroll
    for (int off = 64; off >= 1; off >>= 1) {
        if (t < off) sd[t] += sd[t + off];
        __syncthreads();
    }
    if (t == 0) atomicAdd(&g_loss, sd[0]);
}

// ---- rescore flagged rows with the exact (R10-bitwise) recipe ----
__global__ void __launch_bounds__(256, 1)
vq_rescore(const float* __restrict__ z, const float* __restrict__ cb,
           float* __restrict__ out, int B, int out_size) {
    extern __shared__ float sm[];
    float*  s_cb = sm;                      // [256][68]
    float*  s_z  = sm + 256 * 68;           // [8][64]
    double* sdr  = (double*)(s_z + 8 * 64); // [256]

    const int t = threadIdx.x, lane = t & 31, w = t >> 5;
    const unsigned nf = g_nflag;
    const unsigned per = gridDim.x * 8;
    const unsigned T = (nf + per - 1) / per;
    double lacc = 0.0;

    for (unsigned it = 0; it < T; it++) {
        unsigned fi = (blockIdx.x + it * gridDim.x) * 8 + w;
        const bool act = fi < nf;
        long row = act ? (long)g_flist[fi] : 0;
        __syncthreads();
        if (act) {
            s_z[w * 64 + lane]      = z[row * D + lane];
            s_z[w * 64 + 32 + lane] = z[row * D + 32 + lane];
        }
        __syncwarp();
        float z2 = act ? g_z2[row] : 0.f;
        float m1 = FLTMAX; int i1 = 0;

        for (int ch = 0; ch < 4; ch++) {
            __syncthreads();
            for (int i = t; i < 256 * 16; i += 256) {
                int c = i >> 4, f = i & 15;
                *(float4*)(s_cb + (size_t)c * 68 + 4 * f) =
                    *(const float4*)(cb + ((size_t)ch * 256 + c) * D + 4 * f);
            }
            __syncthreads();
            if (act) {
                for (int j = 0; j < 8; j++) {
                    int kl = lane + 32 * j;
                    int k = ch * 256 + kl;
                    const float2* cp = (const float2*)(s_cb + (size_t)kl * 68);
                    float e = 0.f, o = 0.f;
#pragma unroll
                    for (int i2 = 0; i2 < 32; i2++) {
                        float2 c = cp[i2];
                        float2 zz = *(const float2*)(s_z + w * 64 + 2 * i2);
                        e = fmaf(zz.x, c.x, e);
                        o = fmaf(zz.y, c.y, o);
                    }
                    float dv = fmaf(-2.f, e + o, z2) + g_c2[k];
                    if (dv < m1) { m1 = dv; i1 = k; }   // ascending k per lane
                }
            }
        }
        // warp argmin with first-index tie-break
#pragma unroll
        for (int dx = 16; dx >= 1; dx >>= 1) {
            float ov = __shfl_xor_sync(0xffffffffu, m1, dx);
            int   oi = __shfl_xor_sync(0xffffffffu, i1, dx);
            if (ov < m1 || (ov == m1 && oi < i1)) { m1 = ov; i1 = oi; }
        }
        if (act) {
            float c0 = cb[(size_t)i1 * D + lane], c1 = cb[(size_t)i1 * D + 32 + lane];
            out[row * D + lane] = c0;
            out[row * D + 32 + lane] = c1;
            float d0 = c0 - s_z[w * 64 + lane], d1 = c1 - s_z[w * 64 + 32 + lane];
            lacc += (double)(d0 * d0) + (double)(d1 * d1);
            if (lane == 0 && (long)out_size >= (long)B * D + 1 + B)
                out[(long)B * D + 1 + row] = (float)i1;
        }
    }

    __syncthreads();
    sdr[t] = lacc;
    __syncthreads();
#pragma unroll
    for (int off = 128; off >= 1; off >>= 1) {
        if (t < off) sdr[t] += sdr[t + off];
        __syncthreads();
    }
    if (t == 0 && sdr[0] != 0.0) atomicAdd(&g_loss, sdr[0]);
}

__global__ void vq_finish(float* __restrict__ out, int B, int out_size) {
    if ((long)out_size >= (long)B * D + 1) {
        float m = (float)(g_loss / (double)((long)B * D));
        out[(size_t)B * D] = m + 0.25f * m;
    }
}

extern "C" void kernel_launch(void* const* d_in, const int* in_sizes, int n_in,
                              void* d_out, int out_size) {
    const float* z  = (const float*)d_in[0];
    const float* cb = (const float*)d_in[1];
    float* out = (float*)d_out;
    const int B = in_sizes[0] / D;

    const size_t smemM = (size_t)2 * CHUNKM * CSTR * 4 + K_CODES * 4;
    const size_t smemR = (size_t)256 * 68 * 4 + 8 * 64 * 4 + 256 * 8;
    cudaFuncSetAttribute(vq_mma, cudaFuncAttributeMaxDynamicSharedMemorySize, (int)smemM);
    cudaFuncSetAttribute(vq_rescore, cudaFuncAttributeMaxDynamicSharedMemorySize, (int)smemR);

    vq_prep<<<K_CODES, D>>>(cb);
    vq_z2k<<<(B + 127) / 128, 128>>>(z, B);
    vq_cvt<<<K_CODES, 32>>>(cb);
    vq_mma<<<B / 64, 128, smemM>>>(z, cb, out, B, out_size);
    vq_rescore<<<1024, 256, smemR>>>(z, cb, out, B, out_size);
    vq_finish<<<1, 1>>>(out, B, out_size);
}